// round 13
// baseline (speedup 1.0000x reference)
#include <cuda_runtime.h>
#include <cuda_fp16.h>
#include <cstdint>
#include <math.h>

// Problem constants
#define BB   2
#define LL   4096
#define EE   512
#define HH   8
#define DD   64
#define WIN  128
#define NTOK (BB*LL)          // 8192
#define QKVN (3*EE)           // 1536

// ---------------------------------------------------------------------------
// Device scratch (half precision dataflow)
// ---------------------------------------------------------------------------
__device__ __half g_Xh[NTOK*EE];                      // x rounded
__device__ __half g_Wq[QKVN*EE];                      // qkv weights (rounded)
__device__ __half g_Wo[EE*EE];                        // out weights (rounded)
__device__ __half g_Qh[BB*HH*LL*DD];                  // Q rounded (scaled)
__device__ __half g_Kh[BB*HH*LL*DD];                  // K rounded [B,H,L,D]
__device__ __half g_Vt[BB*HH*DD*LL];                  // V transposed [B,H,D,L]
__device__ __half g_Oh[BB*LL*EE];                     // attn out (rounded)

// ---------------------------------------------------------------------------
// Helpers
// ---------------------------------------------------------------------------
__device__ __forceinline__ void mma_f16(float* d, const uint32_t* a,
                                        const uint32_t* b) {
    asm volatile(
        "mma.sync.aligned.m16n8k16.row.col.f32.f16.f16.f32 "
        "{%0,%1,%2,%3}, {%4,%5,%6,%7}, {%8,%9}, {%0,%1,%2,%3};"
        : "+f"(d[0]), "+f"(d[1]), "+f"(d[2]), "+f"(d[3])
        : "r"(a[0]), "r"(a[1]), "r"(a[2]), "r"(a[3]),
          "r"(b[0]), "r"(b[1]));
}

#define LDSM4(r0, r1, r2, r3, addr) \
    asm volatile("ldmatrix.sync.aligned.m8n8.x4.shared.b16 {%0,%1,%2,%3}, [%4];" \
                 : "=r"(r0), "=r"(r1), "=r"(r2), "=r"(r3) : "r"(addr))

__device__ __forceinline__ uint32_t pack_h2(__half a, __half b) {
    return (uint32_t)__half_as_ushort(a) | ((uint32_t)__half_as_ushort(b) << 16);
}

__device__ __forceinline__ uint32_t smem_u32(const void* p) {
    uint32_t a;
    asm("{ .reg .u64 t; cvta.to.shared.u64 t, %1; cvt.u32.u64 %0, t; }"
        : "=r"(a) : "l"(p));
    return a;
}
__device__ __forceinline__ void cp16(uint32_t dst, const void* src) {
    asm volatile("cp.async.ca.shared.global [%0], [%1], 16;"
                 :: "r"(dst), "l"(src));
}
#define CP_COMMIT() asm volatile("cp.async.commit_group;" ::: "memory")

// ---------------------------------------------------------------------------
// Prep: round f32 arrays to half.  which: 0=Wq 1=Wo 2=X
// ---------------------------------------------------------------------------
__global__ __launch_bounds__(256) void prep_round(const float* __restrict__ w,
                                                  int which)
{
    __half* dst = (which == 0) ? g_Wq : (which == 1) ? g_Wo : g_Xh;
    int i = (blockIdx.x * 256 + threadIdx.x) * 4;
    float4 v = *reinterpret_cast<const float4*>(&w[i]);
    uint2 u;
    u.x = pack_h2(__float2half_rn(v.x), __float2half_rn(v.y));
    u.y = pack_h2(__float2half_rn(v.z), __float2half_rn(v.w));
    *reinterpret_cast<uint2*>(&dst[i]) = u;
}

// ---------------------------------------------------------------------------
// fp16 m16n8k16 GEMM: C = Ah[M,K] @ Bh[N,K]^T + bias, K=512.
//   CTA 128x128, BK=64 (8 chunks), 8 warps, warp tile 64x32.
//   2-stage cp.async double buffer (72 KB smem -> 3 CTAs/SM), ldmatrix.x4.
//   Pitch 72 halves (144B ≡ 16 mod 128): LDSM row addresses conflict-free.
// ---------------------------------------------------------------------------
#define HP   72
#define PLH  (128 * HP)                 // halves per plane
#define GEMM_SMEM (4 * PLH * 2)         // 2 stages x (A | B) = 72 KB

__global__ __launch_bounds__(256, 3) void fp16_gemm(
    const float* __restrict__ bias, float* __restrict__ outp, int mode)
{
    extern __shared__ __half smh[];
    const uint32_t sbase = smem_u32(smh);

    const int tid = threadIdx.x;
    const int m0 = blockIdx.y * 128;
    const int n0 = blockIdx.x * 128;

    const __half* Ahg = mode ? g_Oh : g_Xh;
    const __half* Bg  = mode ? g_Wo : g_Wq;

    const int w    = tid >> 5;
    const int lane = tid & 31;
    const int g    = lane >> 2;
    const int c    = lane & 3;
    const int rm   = (w >> 2) * 64;
    const int cn   = (w & 3) * 32;

    // ldmatrix lane-address components
    const int arow = lane & 15;
    const int acol = (lane >> 4) * 8;
    const int bno  = (lane & 7) + ((lane >> 4) << 3);
    const int bko  = ((lane >> 3) & 1) * 8;

    float acc[4][4][4];
    #pragma unroll
    for (int mi = 0; mi < 4; mi++)
        #pragma unroll
        for (int ni = 0; ni < 4; ni++)
            #pragma unroll
            for (int r = 0; r < 4; r++) acc[mi][ni][r] = 0.f;

    const int lrow = tid >> 2;           // 0..63
    const int lcol = (tid & 3) * 16;     // 0,16,32,48 (halves)

    auto issue_chunk = [&](int kc, int p) {
        const __half* a  = Ahg + (size_t)m0 * EE + kc * 64;
        const __half* bb = Bg  + (size_t)n0 * EE + kc * 64;
        const uint32_t sb = sbase + (uint32_t)(p * 2 * PLH * 2);
        #pragma unroll
        for (int i = 0; i < 2; i++) {
            int row = lrow + i * 64;
            uint32_t so = (uint32_t)((row * HP + lcol) * 2);
            cp16(sb + so,                a  + (size_t)row * EE + lcol);
            cp16(sb + so + 16,           a  + (size_t)row * EE + lcol + 8);
            cp16(sb + PLH * 2 + so,      bb + (size_t)row * EE + lcol);
            cp16(sb + PLH * 2 + so + 16, bb + (size_t)row * EE + lcol + 8);
        }
    };

    issue_chunk(0, 0); CP_COMMIT();

    for (int kc = 0; kc < 8; kc++) {
        const int p = kc & 1;
        asm volatile("cp.async.wait_group 0;" ::: "memory");
        __syncthreads();

        if (kc + 1 < 8) {
            issue_chunk(kc + 1, p ^ 1);
            CP_COMMIT();
        }

        const uint32_t sA = sbase + (uint32_t)(p * 2 * PLH * 2);
        const uint32_t sB = sA + (uint32_t)(PLH * 2);

        #pragma unroll
        for (int ks = 0; ks < 4; ks++) {
            uint32_t af[4][4], bf[4][2];
            #pragma unroll
            for (int mi = 0; mi < 4; mi++) {
                uint32_t ad = sA + (uint32_t)(((rm + mi * 16 + arow) * HP
                                               + ks * 16 + acol) * 2);
                LDSM4(af[mi][0], af[mi][1], af[mi][2], af[mi][3], ad);
            }
            #pragma unroll
            for (int p2 = 0; p2 < 2; p2++) {
                uint32_t bd = sB + (uint32_t)(((cn + p2 * 16 + bno) * HP
                                               + ks * 16 + bko) * 2);
                LDSM4(bf[2 * p2][0], bf[2 * p2][1],
                      bf[2 * p2 + 1][0], bf[2 * p2 + 1][1], bd);
            }
            #pragma unroll
            for (int mi = 0; mi < 4; mi++)
                #pragma unroll
                for (int ni = 0; ni < 4; ni++)
                    mma_f16(acc[mi][ni], af[mi], bf[ni]);
        }
    }

    float bv[4][2];
    #pragma unroll
    for (int ni = 0; ni < 4; ni++) {
        int gn = n0 + cn + ni * 8 + 2 * c;
        bv[ni][0] = bias[gn];
        bv[ni][1] = bias[gn + 1];
    }

    if (mode == 0) {
        const int gnb = n0 + cn;
        const int sel = gnb >> 9;                  // 0=Q 1=K 2=V
        const int h   = (gnb >> 6) & 7;
        #pragma unroll
        for (int mi = 0; mi < 4; mi++) {
            #pragma unroll
            for (int half = 0; half < 2; half++) {
                int gm  = m0 + rm + mi * 16 + g + half * 8;
                int bat = gm >> 12;
                int l   = gm & (LL - 1);
                #pragma unroll
                for (int ni = 0; ni < 4; ni++) {
                    int gn = n0 + cn + ni * 8 + 2 * c;
                    int d  = gn & 63;
                    float f0 = acc[mi][ni][half * 2 + 0] + bv[ni][0];
                    float f1 = acc[mi][ni][half * 2 + 1] + bv[ni][1];
                    if (sel == 0) {
                        f0 *= 0.125f; f1 *= 0.125f;
                        size_t rb = (((size_t)(bat * HH + h) * LL) + l) * DD + d;
                        *reinterpret_cast<uint32_t*>(&g_Qh[rb]) =
                            pack_h2(__float2half_rn(f0), __float2half_rn(f1));
                    } else if (sel == 1) {
                        size_t rb = (((size_t)(bat * HH + h) * LL) + l) * DD + d;
                        *reinterpret_cast<uint32_t*>(&g_Kh[rb]) =
                            pack_h2(__float2half_rn(f0), __float2half_rn(f1));
                    } else {
                        size_t vb = (((size_t)(bat * HH + h) * DD) + d) * LL + l;
                        g_Vt[vb]      = __float2half_rn(f0);
                        g_Vt[vb + LL] = __float2half_rn(f1);
                    }
                }
            }
        }
    } else {
        #pragma unroll
        for (int mi = 0; mi < 4; mi++) {
            #pragma unroll
            for (int half = 0; half < 2; half++) {
                int gm = m0 + rm + mi * 16 + g + half * 8;
                #pragma unroll
                for (int ni = 0; ni < 4; ni++) {
                    int gn = n0 + cn + ni * 8 + 2 * c;
                    float2 o;
                    o.x = acc[mi][ni][half * 2 + 0] + bv[ni][0];
                    o.y = acc[mi][ni][half * 2 + 1] + bv[ni][1];
                    *reinterpret_cast<float2*>(&outp[(size_t)gm * EE + gn]) = o;
                }
            }
        }
    }
}

// ---------------------------------------------------------------------------
// Banded flash attention, fp16 m16n8k16, single-rounded operands, ldmatrix.
//   Planes (half, pitch 72): Qs | Ks | Vt | Ph. 36 KB -> 4+ CTAs/SM.
// ---------------------------------------------------------------------------
#define AP 72
#define HPL (64 * AP)
#define ATTN_SMEM (4 * HPL * 2)

__global__ __launch_bounds__(128, 4) void attn_mma()
{
    extern __shared__ __half smq[];
    const uint32_t sQ = smem_u32(smq);
    const uint32_t sK = sQ + 1 * HPL * 2;
    const uint32_t sV = sQ + 2 * HPL * 2;
    const uint32_t sP = sQ + 3 * HPL * 2;
    __half* Qs = smq;
    __half* Ks = smq + 1 * HPL;
    __half* Vt = smq + 2 * HPL;
    __half* Ph = smq + 3 * HPL;

    const int q0 = blockIdx.x * 64;
    const int h  = blockIdx.y;
    const int b  = blockIdx.z;
    const int tid  = threadIdx.x;
    const int w    = tid >> 5;
    const int lane = tid & 31;
    const int g    = lane >> 2;
    const int c    = lane & 3;

    const int arow = lane & 15;
    const int acol = (lane >> 4) * 8;
    const int bno  = (lane & 7) + ((lane >> 4) << 3);
    const int bko  = ((lane >> 3) & 1) * 8;

    const size_t khead = ((size_t)(b * HH + h) * LL) * DD;
    const size_t vhead = ((size_t)(b * HH + h) * DD) * LL;

    // ---- stage Q (pure copy) ----
    #pragma unroll
    for (int i = 0; i < 4; i++) {
        int u = tid + i * 128;
        int row = u >> 3;
        int seg = (u & 7) * 8;
        *reinterpret_cast<uint4*>(&Qs[row * AP + seg]) =
            *reinterpret_cast<const uint4*>(&g_Qh[khead + (size_t)(q0 + row) * DD + seg]);
    }

    float om[2] = {-1e30f, -1e30f};
    float ol[2] = {0.f, 0.f};
    float oacc[8][4];
    #pragma unroll
    for (int nt = 0; nt < 8; nt++)
        #pragma unroll
        for (int r = 0; r < 4; r++) oacc[nt][r] = 0.f;

    __syncthreads();

    const int row_lo = 16 * w + g;
    const int q_lo = q0 + row_lo;
    const int q_hi = q_lo + 8;

    for (int ch = 0; ch < 5; ch++) {
        const int kcc = q0 - 128 + ch * 64;
        if (kcc + 64 <= 0 || kcc >= LL) continue;

        // ---- stage K (natural) and V (pre-transposed) — pure copies ----
        #pragma unroll
        for (int i = 0; i < 4; i++) {
            int u = tid + i * 128;
            int row = u >> 3;
            int seg = (u & 7) * 8;
            int kk = min(max(kcc + row, 0), LL - 1);
            *reinterpret_cast<uint4*>(&Ks[row * AP + seg]) =
                *reinterpret_cast<const uint4*>(&g_Kh[khead + (size_t)kk * DD + seg]);
            int kb = min(max(kcc + seg, 0), LL - 8);
            *reinterpret_cast<uint4*>(&Vt[row * AP + seg]) =
                *reinterpret_cast<const uint4*>(&g_Vt[vhead + (size_t)row * LL + kb]);
        }
        __syncthreads();

        // ---- scores: Q @ K^T (ldmatrix + single MMA per tile) ----
        float sacc[8][4];
        #pragma unroll
        for (int nt = 0; nt < 8; nt++)
            #pragma unroll
            for (int r = 0; r < 4; r++) sacc[nt][r] = 0.f;

        #pragma unroll
        for (int ks = 0; ks < 4; ks++) {
            uint32_t af[4], kb2[8][2];
            uint32_t ad = sQ + (uint32_t)(((16 * w + arow) * AP + ks * 16 + acol) * 2);
            LDSM4(af[0], af[1], af[2], af[3], ad);
            #pragma unroll
            for (int p2 = 0; p2 < 4; p2++) {
                uint32_t bd = sK + (uint32_t)(((p2 * 16 + bno) * AP + ks * 16 + bko) * 2);
                LDSM4(kb2[2 * p2][0], kb2[2 * p2][1],
                      kb2[2 * p2 + 1][0], kb2[2 * p2 + 1][1], bd);
            }
            #pragma unroll
            for (int nt = 0; nt < 8; nt++)
                mma_f16(sacc[nt], af, kb2[nt]);
        }

        // ---- mask ----
        #pragma unroll
        for (int nt = 0; nt < 8; nt++) {
            #pragma unroll
            for (int r = 0; r < 4; r++) {
                int key = kcc + nt * 8 + 2 * c + (r & 1);
                int q   = (r >> 1) ? q_hi : q_lo;
                int dlt = q - key;
                bool ok = (key >= 0) && (key < LL) && (dlt != 0) &&
                          (dlt <= WIN) && (dlt >= -WIN);
                if (!ok) sacc[nt][r] = -1e30f;
            }
        }

        // ---- online softmax; write P (single fp16) ----
        float mx0 = -1e30f, mx1 = -1e30f;
        #pragma unroll
        for (int nt = 0; nt < 8; nt++) {
            mx0 = fmaxf(mx0, fmaxf(sacc[nt][0], sacc[nt][1]));
            mx1 = fmaxf(mx1, fmaxf(sacc[nt][2], sacc[nt][3]));
        }
        mx0 = fmaxf(mx0, __shfl_xor_sync(0xffffffffu, mx0, 1));
        mx0 = fmaxf(mx0, __shfl_xor_sync(0xffffffffu, mx0, 2));
        mx1 = fmaxf(mx1, __shfl_xor_sync(0xffffffffu, mx1, 1));
        mx1 = fmaxf(mx1, __shfl_xor_sync(0xffffffffu, mx1, 2));

        float m0n = fmaxf(om[0], mx0);
        float m1n = fmaxf(om[1], mx1);
        float alpha0 = __expf(om[0] - m0n);
        float alpha1 = __expf(om[1] - m1n);

        float sum0 = 0.f, sum1 = 0.f;
        #pragma unroll
        for (int nt = 0; nt < 8; nt++) {
            float p0 = __expf(sacc[nt][0] - m0n);
            float p1 = __expf(sacc[nt][1] - m0n);
            float p2 = __expf(sacc[nt][2] - m1n);
            float p3 = __expf(sacc[nt][3] - m1n);
            sum0 += p0 + p1;
            sum1 += p2 + p3;
            const int pi_lo = row_lo * AP + nt * 8 + 2 * c;
            const int pi_hi = pi_lo + 8 * AP;
            *reinterpret_cast<uint32_t*>(&Ph[pi_lo]) =
                pack_h2(__float2half_rn(p0), __float2half_rn(p1));
            *reinterpret_cast<uint32_t*>(&Ph[pi_hi]) =
                pack_h2(__float2half_rn(p2), __float2half_rn(p3));
        }
        sum0 += __shfl_xor_sync(0xffffffffu, sum0, 1);
        sum0 += __shfl_xor_sync(0xffffffffu, sum0, 2);
        sum1 += __shfl_xor_sync(0xffffffffu, sum1, 1);
        sum1 += __shfl_xor_sync(0xffffffffu, sum1, 2);

        ol[0] = ol[0] * alpha0 + sum0;
        ol[1] = ol[1] * alpha1 + sum1;
        om[0] = m0n;
        om[1] = m1n;

        #pragma unroll
        for (int nt = 0; nt < 8; nt++) {
            oacc[nt][0] *= alpha0;
            oacc[nt][1] *= alpha0;
            oacc[nt][2] *= alpha1;
            oacc[nt][3] *= alpha1;
        }
        __syncwarp();   // P rows are warp-private

        // ---- O += P @ V (ldmatrix + single MMA per tile) ----
        #pragma unroll
        for (int ks = 0; ks < 4; ks++) {
            uint32_t af[4], vb2[8][2];
            uint32_t ad = sP + (uint32_t)(((16 * w + arow) * AP + ks * 16 + acol) * 2);
            LDSM4(af[0], af[1], af[2], af[3], ad);
            #pragma unroll
            for (int p2 = 0; p2 < 4; p2++) {
                uint32_t bd = sV + (uint32_t)(((p2 * 16 + bno) * AP + ks * 16 + bko) * 2);
                LDSM4(vb2[2 * p2][0], vb2[2 * p2][1],
                      vb2[2 * p2 + 1][0], vb2[2 * p2 + 1][1], bd);
            }
            #pragma unroll
            for (int nt = 0; nt < 8; nt++)
                mma_f16(oacc[nt], af, vb2[nt]);
        }
        __syncthreads();   // protect Ks/Vt before next chunk staging
    }

    // ---- epilogue: normalize, round, write Oh [B,L,E] ----
    const float inv0 = 1.f / ol[0];
    const float inv1 = 1.f / ol[1];
    const size_t base_lo = ((size_t)(b * LL + q_lo)) * EE + h * DD;
    const size_t base_hi = ((size_t)(b * LL + q_hi)) * EE + h * DD;
    #pragma unroll
    for (int nt = 0; nt < 8; nt++) {
        int d = nt * 8 + 2 * c;
        *reinterpret_cast<uint32_t*>(&g_Oh[base_lo + d]) =
            pack_h2(__float2half_rn(oacc[nt][0] * inv0),
                    __float2half_rn(oacc[nt][1] * inv0));
        *reinterpret_cast<uint32_t*>(&g_Oh[base_hi + d]) =
            pack_h2(__float2half_rn(oacc[nt][2] * inv1),
                    __float2half_rn(oacc[nt][3] * inv1));
    }
}

// ---------------------------------------------------------------------------
// Entry point
// ---------------------------------------------------------------------------
extern "C" void kernel_launch(void* const* d_in, const int* in_sizes, int n_in,
                              void* d_out, int out_size)
{
    const float* x    = (const float*)d_in[0];   // [B,L,E]
    const float* wqkv = (const float*)d_in[1];   // [3E,E]
    const float* bqkv = (const float*)d_in[2];   // [3E]
    const float* wout = (const float*)d_in[3];   // [E,E]
    const float* bout = (const float*)d_in[4];   // [E]
    float* out = (float*)d_out;                  // [B,L,E]

    (void)in_sizes; (void)n_in; (void)out_size;

    cudaFuncSetAttribute(fp16_gemm, cudaFuncAttributeMaxDynamicSharedMemorySize,
                         GEMM_SMEM);
    cudaFuncSetAttribute(attn_mma, cudaFuncAttributeMaxDynamicSharedMemorySize,
                         ATTN_SMEM);

    // prep: round weights + x to half
    prep_round<<<QKVN * EE / 1024, 256>>>(wqkv, 0);
    prep_round<<<EE * EE / 1024, 256>>>(wout, 1);
    prep_round<<<NTOK * EE / 1024, 256>>>(x, 2);

    // QKV projection
    fp16_gemm<<<dim3(QKVN / 128, NTOK / 128), 256, GEMM_SMEM>>>(bqkv, nullptr, 0);

    // banded attention
    attn_mma<<<dim3(LL / 64, HH, BB), 128, ATTN_SMEM>>>();

    // out projection
    fp16_gemm<<<dim3(EE / 128, NTOK / 128), 256, GEMM_SMEM>>>(bout, out, 1);
}

// round 14
// speedup vs baseline: 1.6301x; 1.6301x over previous
#include <cuda_runtime.h>
#include <cuda_fp16.h>
#include <cstdint>
#include <math.h>

// Problem constants
#define BB   2
#define LL   4096
#define EE   512
#define HH   8
#define DD   64
#define WIN  128
#define NTOK (BB*LL)          // 8192
#define QKVN (3*EE)           // 1536

// ---------------------------------------------------------------------------
// Device scratch (half precision dataflow)
// ---------------------------------------------------------------------------
__device__ __half g_Xh[NTOK*EE];                      // x rounded
__device__ __half g_Wq[QKVN*EE];                      // qkv weights (rounded)
__device__ __half g_Wo[EE*EE];                        // out weights (rounded)
__device__ __half g_Qh[BB*HH*LL*DD];                  // Q rounded (scaled)
__device__ __half g_Kh[BB*HH*LL*DD];                  // K rounded [B,H,L,D]
__device__ __half g_Vt[BB*HH*DD*LL];                  // V transposed [B,H,D,L]
__device__ __half g_Oh[BB*LL*EE];                     // attn out (rounded)

// ---------------------------------------------------------------------------
// Helpers
// ---------------------------------------------------------------------------
__device__ __forceinline__ void mma_f16(float* d, const uint32_t* a,
                                        const uint32_t* b) {
    asm volatile(
        "mma.sync.aligned.m16n8k16.row.col.f32.f16.f16.f32 "
        "{%0,%1,%2,%3}, {%4,%5,%6,%7}, {%8,%9}, {%0,%1,%2,%3};"
        : "+f"(d[0]), "+f"(d[1]), "+f"(d[2]), "+f"(d[3])
        : "r"(a[0]), "r"(a[1]), "r"(a[2]), "r"(a[3]),
          "r"(b[0]), "r"(b[1]));
}

#define LDSM4(r0, r1, r2, r3, addr) \
    asm volatile("ldmatrix.sync.aligned.m8n8.x4.shared.b16 {%0,%1,%2,%3}, [%4];" \
                 : "=r"(r0), "=r"(r1), "=r"(r2), "=r"(r3) : "r"(addr))

__device__ __forceinline__ uint32_t pack_h2(__half a, __half b) {
    return (uint32_t)__half_as_ushort(a) | ((uint32_t)__half_as_ushort(b) << 16);
}

__device__ __forceinline__ uint32_t smem_u32(const void* p) {
    uint32_t a;
    asm("{ .reg .u64 t; cvta.to.shared.u64 t, %1; cvt.u32.u64 %0, t; }"
        : "=r"(a) : "l"(p));
    return a;
}
__device__ __forceinline__ void cp16(uint32_t dst, const void* src) {
    asm volatile("cp.async.ca.shared.global [%0], [%1], 16;"
                 :: "r"(dst), "l"(src));
}
#define CP_COMMIT() asm volatile("cp.async.commit_group;" ::: "memory")

// ---------------------------------------------------------------------------
// Prep: round f32 arrays to half.  which: 0=Wq 1=Wo 2=X
// ---------------------------------------------------------------------------
__global__ __launch_bounds__(256) void prep_round(const float* __restrict__ w,
                                                  int which)
{
    __half* dst = (which == 0) ? g_Wq : (which == 1) ? g_Wo : g_Xh;
    int i = (blockIdx.x * 256 + threadIdx.x) * 4;
    float4 v = *reinterpret_cast<const float4*>(&w[i]);
    uint2 u;
    u.x = pack_h2(__float2half_rn(v.x), __float2half_rn(v.y));
    u.y = pack_h2(__float2half_rn(v.z), __float2half_rn(v.w));
    *reinterpret_cast<uint2*>(&dst[i]) = u;
}

// ---------------------------------------------------------------------------
// fp16 m16n8k16 GEMM: C = Ah[M,K] @ Bh[N,K]^T + bias, K=512.
//   CTA 128x128, BK=64 (8 chunks), 8 warps, warp tile 64x32.
//   2-stage cp.async double buffer, XOR-swizzled planes (128x64 halves,
//   granule ^= row&7 -> ldmatrix conflict-free, no padding): 64 KB smem.
//   Inner loop: B fragments resident, A fragment loaded per-mi (low regs)
//   -> 3 CTAs/SM.
// ---------------------------------------------------------------------------
#define PLB  16384                       // bytes per plane (128*64*2)
#define GEMM_SMEM (4 * PLB)              // 2 stages x (A | B) = 64 KB

__global__ __launch_bounds__(256, 3) void fp16_gemm(
    const float* __restrict__ bias, float* __restrict__ outp, int mode)
{
    extern __shared__ __half smh[];
    const uint32_t sbase = smem_u32(smh);

    const int tid = threadIdx.x;
    const int m0 = blockIdx.y * 128;
    const int n0 = blockIdx.x * 128;

    const __half* Ahg = mode ? g_Oh : g_Xh;
    const __half* Bg  = mode ? g_Wo : g_Wq;

    const int w    = tid >> 5;
    const int lane = tid & 31;
    const int g    = lane >> 2;
    const int c    = lane & 3;
    const int rm   = (w >> 2) * 64;
    const int cn   = (w & 3) * 32;

    // ldmatrix lane-address components
    const int arow = lane & 15;          // A: row within 16
    const int ag   = lane >> 4;          // A: granule half (0/1)
    const int bno  = (lane & 7) + ((lane >> 4) << 3);   // B: row within 16
    const int bg   = (lane >> 3) & 1;    // B: granule half (0/1)

    float acc[4][4][4];
    #pragma unroll
    for (int mi = 0; mi < 4; mi++)
        #pragma unroll
        for (int ni = 0; ni < 4; ni++)
            #pragma unroll
            for (int r = 0; r < 4; r++) acc[mi][ni][r] = 0.f;

    auto issue_chunk = [&](int kc, int p) {
        const __half* a  = Ahg + (size_t)m0 * EE + kc * 64;
        const __half* bb = Bg  + (size_t)n0 * EE + kc * 64;
        const uint32_t sb = sbase + (uint32_t)(p * 2 * PLB);
        #pragma unroll
        for (int i = 0; i < 4; i++) {
            int u   = tid + i * 256;     // 0..1023
            int row = u >> 3;
            int gi  = u & 7;
            uint32_t so = (uint32_t)((row * 64 + ((gi ^ (row & 7)) * 8)) * 2);
            cp16(sb + so,       a  + (size_t)row * EE + gi * 8);
            cp16(sb + PLB + so, bb + (size_t)row * EE + gi * 8);
        }
    };

    issue_chunk(0, 0); CP_COMMIT();

    for (int kc = 0; kc < 8; kc++) {
        const int p = kc & 1;
        asm volatile("cp.async.wait_group 0;" ::: "memory");
        __syncthreads();

        if (kc + 1 < 8) {
            issue_chunk(kc + 1, p ^ 1);
            CP_COMMIT();
        }

        const uint32_t sA = sbase + (uint32_t)(p * 2 * PLB);
        const uint32_t sB = sA + (uint32_t)PLB;

        #pragma unroll
        for (int ks = 0; ks < 4; ks++) {
            uint32_t bf[4][2];
            #pragma unroll
            for (int p2 = 0; p2 < 2; p2++) {
                int row = cn + p2 * 16 + bno;
                int gb  = (ks * 2 + bg) ^ (row & 7);
                uint32_t bd = sB + (uint32_t)((row * 64 + gb * 8) * 2);
                LDSM4(bf[2 * p2][0], bf[2 * p2][1],
                      bf[2 * p2 + 1][0], bf[2 * p2 + 1][1], bd);
            }
            #pragma unroll
            for (int mi = 0; mi < 4; mi++) {
                uint32_t af[4];
                int row = rm + mi * 16 + arow;
                int ga  = (ks * 2 + ag) ^ (row & 7);
                uint32_t ad = sA + (uint32_t)((row * 64 + ga * 8) * 2);
                LDSM4(af[0], af[1], af[2], af[3], ad);
                #pragma unroll
                for (int ni = 0; ni < 4; ni++)
                    mma_f16(acc[mi][ni], af, bf[ni]);
            }
        }
    }

    float bv[4][2];
    #pragma unroll
    for (int ni = 0; ni < 4; ni++) {
        int gn = n0 + cn + ni * 8 + 2 * c;
        bv[ni][0] = bias[gn];
        bv[ni][1] = bias[gn + 1];
    }

    if (mode == 0) {
        const int gnb = n0 + cn;
        const int sel = gnb >> 9;                  // 0=Q 1=K 2=V
        const int h   = (gnb >> 6) & 7;
        #pragma unroll
        for (int mi = 0; mi < 4; mi++) {
            #pragma unroll
            for (int half = 0; half < 2; half++) {
                int gm  = m0 + rm + mi * 16 + g + half * 8;
                int bat = gm >> 12;
                int l   = gm & (LL - 1);
                #pragma unroll
                for (int ni = 0; ni < 4; ni++) {
                    int gn = n0 + cn + ni * 8 + 2 * c;
                    int d  = gn & 63;
                    float f0 = acc[mi][ni][half * 2 + 0] + bv[ni][0];
                    float f1 = acc[mi][ni][half * 2 + 1] + bv[ni][1];
                    if (sel == 0) {
                        f0 *= 0.125f; f1 *= 0.125f;
                        size_t rb = (((size_t)(bat * HH + h) * LL) + l) * DD + d;
                        *reinterpret_cast<uint32_t*>(&g_Qh[rb]) =
                            pack_h2(__float2half_rn(f0), __float2half_rn(f1));
                    } else if (sel == 1) {
                        size_t rb = (((size_t)(bat * HH + h) * LL) + l) * DD + d;
                        *reinterpret_cast<uint32_t*>(&g_Kh[rb]) =
                            pack_h2(__float2half_rn(f0), __float2half_rn(f1));
                    } else {
                        size_t vb = (((size_t)(bat * HH + h) * DD) + d) * LL + l;
                        g_Vt[vb]      = __float2half_rn(f0);
                        g_Vt[vb + LL] = __float2half_rn(f1);
                    }
                }
            }
        }
    } else {
        #pragma unroll
        for (int mi = 0; mi < 4; mi++) {
            #pragma unroll
            for (int half = 0; half < 2; half++) {
                int gm = m0 + rm + mi * 16 + g + half * 8;
                #pragma unroll
                for (int ni = 0; ni < 4; ni++) {
                    int gn = n0 + cn + ni * 8 + 2 * c;
                    float2 o;
                    o.x = acc[mi][ni][half * 2 + 0] + bv[ni][0];
                    o.y = acc[mi][ni][half * 2 + 1] + bv[ni][1];
                    *reinterpret_cast<float2*>(&outp[(size_t)gm * EE + gn]) = o;
                }
            }
        }
    }
}

// ---------------------------------------------------------------------------
// Banded flash attention, fp16 m16n8k16, single-rounded operands, ldmatrix.
//   Planes (half, pitch 72): Qs | Ks | Vt | Ph. 36 KB -> 4+ CTAs/SM.
//   (Byte-identical to round 12 — known good.)
// ---------------------------------------------------------------------------
#define AP 72
#define HPL (64 * AP)
#define ATTN_SMEM (4 * HPL * 2)

__global__ __launch_bounds__(128, 4) void attn_mma()
{
    extern __shared__ __half smq[];
    const uint32_t sQ = smem_u32(smq);
    const uint32_t sK = sQ + 1 * HPL * 2;
    const uint32_t sV = sQ + 2 * HPL * 2;
    const uint32_t sP = sQ + 3 * HPL * 2;
    __half* Qs = smq;
    __half* Ks = smq + 1 * HPL;
    __half* Vt = smq + 2 * HPL;
    __half* Ph = smq + 3 * HPL;

    const int q0 = blockIdx.x * 64;
    const int h  = blockIdx.y;
    const int b  = blockIdx.z;
    const int tid  = threadIdx.x;
    const int w    = tid >> 5;
    const int lane = tid & 31;
    const int g    = lane >> 2;
    const int c    = lane & 3;

    const int arow = lane & 15;
    const int acol = (lane >> 4) * 8;
    const int bno  = (lane & 7) + ((lane >> 4) << 3);
    const int bko  = ((lane >> 3) & 1) * 8;

    const size_t khead = ((size_t)(b * HH + h) * LL) * DD;
    const size_t vhead = ((size_t)(b * HH + h) * DD) * LL;

    // ---- stage Q (pure copy) ----
    #pragma unroll
    for (int i = 0; i < 4; i++) {
        int u = tid + i * 128;
        int row = u >> 3;
        int seg = (u & 7) * 8;
        *reinterpret_cast<uint4*>(&Qs[row * AP + seg]) =
            *reinterpret_cast<const uint4*>(&g_Qh[khead + (size_t)(q0 + row) * DD + seg]);
    }

    float om[2] = {-1e30f, -1e30f};
    float ol[2] = {0.f, 0.f};
    float oacc[8][4];
    #pragma unroll
    for (int nt = 0; nt < 8; nt++)
        #pragma unroll
        for (int r = 0; r < 4; r++) oacc[nt][r] = 0.f;

    __syncthreads();

    const int row_lo = 16 * w + g;
    const int q_lo = q0 + row_lo;
    const int q_hi = q_lo + 8;

    for (int ch = 0; ch < 5; ch++) {
        const int kcc = q0 - 128 + ch * 64;
        if (kcc + 64 <= 0 || kcc >= LL) continue;

        // ---- stage K (natural) and V (pre-transposed) — pure copies ----
        #pragma unroll
        for (int i = 0; i < 4; i++) {
            int u = tid + i * 128;
            int row = u >> 3;
            int seg = (u & 7) * 8;
            int kk = min(max(kcc + row, 0), LL - 1);
            *reinterpret_cast<uint4*>(&Ks[row * AP + seg]) =
                *reinterpret_cast<const uint4*>(&g_Kh[khead + (size_t)kk * DD + seg]);
            int kb = min(max(kcc + seg, 0), LL - 8);
            *reinterpret_cast<uint4*>(&Vt[row * AP + seg]) =
                *reinterpret_cast<const uint4*>(&g_Vt[vhead + (size_t)row * LL + kb]);
        }
        __syncthreads();

        // ---- scores: Q @ K^T (ldmatrix + single MMA per tile) ----
        float sacc[8][4];
        #pragma unroll
        for (int nt = 0; nt < 8; nt++)
            #pragma unroll
            for (int r = 0; r < 4; r++) sacc[nt][r] = 0.f;

        #pragma unroll
        for (int ks = 0; ks < 4; ks++) {
            uint32_t af[4], kb2[8][2];
            uint32_t ad = sQ + (uint32_t)(((16 * w + arow) * AP + ks * 16 + acol) * 2);
            LDSM4(af[0], af[1], af[2], af[3], ad);
            #pragma unroll
            for (int p2 = 0; p2 < 4; p2++) {
                uint32_t bd = sK + (uint32_t)(((p2 * 16 + bno) * AP + ks * 16 + bko) * 2);
                LDSM4(kb2[2 * p2][0], kb2[2 * p2][1],
                      kb2[2 * p2 + 1][0], kb2[2 * p2 + 1][1], bd);
            }
            #pragma unroll
            for (int nt = 0; nt < 8; nt++)
                mma_f16(sacc[nt], af, kb2[nt]);
        }

        // ---- mask ----
        #pragma unroll
        for (int nt = 0; nt < 8; nt++) {
            #pragma unroll
            for (int r = 0; r < 4; r++) {
                int key = kcc + nt * 8 + 2 * c + (r & 1);
                int q   = (r >> 1) ? q_hi : q_lo;
                int dlt = q - key;
                bool ok = (key >= 0) && (key < LL) && (dlt != 0) &&
                          (dlt <= WIN) && (dlt >= -WIN);
                if (!ok) sacc[nt][r] = -1e30f;
            }
        }

        // ---- online softmax; write P (single fp16) ----
        float mx0 = -1e30f, mx1 = -1e30f;
        #pragma unroll
        for (int nt = 0; nt < 8; nt++) {
            mx0 = fmaxf(mx0, fmaxf(sacc[nt][0], sacc[nt][1]));
            mx1 = fmaxf(mx1, fmaxf(sacc[nt][2], sacc[nt][3]));
        }
        mx0 = fmaxf(mx0, __shfl_xor_sync(0xffffffffu, mx0, 1));
        mx0 = fmaxf(mx0, __shfl_xor_sync(0xffffffffu, mx0, 2));
        mx1 = fmaxf(mx1, __shfl_xor_sync(0xffffffffu, mx1, 1));
        mx1 = fmaxf(mx1, __shfl_xor_sync(0xffffffffu, mx1, 2));

        float m0n = fmaxf(om[0], mx0);
        float m1n = fmaxf(om[1], mx1);
        float alpha0 = __expf(om[0] - m0n);
        float alpha1 = __expf(om[1] - m1n);

        float sum0 = 0.f, sum1 = 0.f;
        #pragma unroll
        for (int nt = 0; nt < 8; nt++) {
            float p0 = __expf(sacc[nt][0] - m0n);
            float p1 = __expf(sacc[nt][1] - m0n);
            float p2 = __expf(sacc[nt][2] - m1n);
            float p3 = __expf(sacc[nt][3] - m1n);
            sum0 += p0 + p1;
            sum1 += p2 + p3;
            const int pi_lo = row_lo * AP + nt * 8 + 2 * c;
            const int pi_hi = pi_lo + 8 * AP;
            *reinterpret_cast<uint32_t*>(&Ph[pi_lo]) =
                pack_h2(__float2half_rn(p0), __float2half_rn(p1));
            *reinterpret_cast<uint32_t*>(&Ph[pi_hi]) =
                pack_h2(__float2half_rn(p2), __float2half_rn(p3));
        }
        sum0 += __shfl_xor_sync(0xffffffffu, sum0, 1);
        sum0 += __shfl_xor_sync(0xffffffffu, sum0, 2);
        sum1 += __shfl_xor_sync(0xffffffffu, sum1, 1);
        sum1 += __shfl_xor_sync(0xffffffffu, sum1, 2);

        ol[0] = ol[0] * alpha0 + sum0;
        ol[1] = ol[1] * alpha1 + sum1;
        om[0] = m0n;
        om[1] = m1n;

        #pragma unroll
        for (int nt = 0; nt < 8; nt++) {
            oacc[nt][0] *= alpha0;
            oacc[nt][1] *= alpha0;
            oacc[nt][2] *= alpha1;
            oacc[nt][3] *= alpha1;
        }
        __syncwarp();   // P rows are warp-private

        // ---- O += P @ V (ldmatrix + single MMA per tile) ----
        #pragma unroll
        for (int ks = 0; ks < 4; ks++) {
            uint32_t af[4], vb2[8][2];
            uint32_t ad = sP + (uint32_t)(((16 * w + arow) * AP + ks * 16 + acol) * 2);
            LDSM4(af[0], af[1], af[2], af[3], ad);
            #pragma unroll
            for (int p2 = 0; p2 < 4; p2++) {
                uint32_t bd = sV + (uint32_t)(((p2 * 16 + bno) * AP + ks * 16 + bko) * 2);
                LDSM4(vb2[2 * p2][0], vb2[2 * p2][1],
                      vb2[2 * p2 + 1][0], vb2[2 * p2 + 1][1], bd);
            }
            #pragma unroll
            for (int nt = 0; nt < 8; nt++)
                mma_f16(oacc[nt], af, vb2[nt]);
        }
        __syncthreads();   // protect Ks/Vt before next chunk staging
    }

    // ---- epilogue: normalize, round, write Oh [B,L,E] ----
    const float inv0 = 1.f / ol[0];
    const float inv1 = 1.f / ol[1];
    const size_t base_lo = ((size_t)(b * LL + q_lo)) * EE + h * DD;
    const size_t base_hi = ((size_t)(b * LL + q_hi)) * EE + h * DD;
    #pragma unroll
    for (int nt = 0; nt < 8; nt++) {
        int d = nt * 8 + 2 * c;
        *reinterpret_cast<uint32_t*>(&g_Oh[base_lo + d]) =
            pack_h2(__float2half_rn(oacc[nt][0] * inv0),
                    __float2half_rn(oacc[nt][1] * inv0));
        *reinterpret_cast<uint32_t*>(&g_Oh[base_hi + d]) =
            pack_h2(__float2half_rn(oacc[nt][2] * inv1),
                    __float2half_rn(oacc[nt][3] * inv1));
    }
}

// ---------------------------------------------------------------------------
// Entry point
// ---------------------------------------------------------------------------
extern "C" void kernel_launch(void* const* d_in, const int* in_sizes, int n_in,
                              void* d_out, int out_size)
{
    const float* x    = (const float*)d_in[0];   // [B,L,E]
    const float* wqkv = (const float*)d_in[1];   // [3E,E]
    const float* bqkv = (const float*)d_in[2];   // [3E]
    const float* wout = (const float*)d_in[3];   // [E,E]
    const float* bout = (const float*)d_in[4];   // [E]
    float* out = (float*)d_out;                  // [B,L,E]

    (void)in_sizes; (void)n_in; (void)out_size;

    cudaFuncSetAttribute(fp16_gemm, cudaFuncAttributeMaxDynamicSharedMemorySize,
                         GEMM_SMEM);
    cudaFuncSetAttribute(attn_mma, cudaFuncAttributeMaxDynamicSharedMemorySize,
                         ATTN_SMEM);

    // prep: round weights + x to half
    prep_round<<<QKVN * EE / 1024, 256>>>(wqkv, 0);
    prep_round<<<EE * EE / 1024, 256>>>(wout, 1);
    prep_round<<<NTOK * EE / 1024, 256>>>(x, 2);

    // QKV projection
    fp16_gemm<<<dim3(QKVN / 128, NTOK / 128), 256, GEMM_SMEM>>>(bqkv, nullptr, 0);

    // banded attention
    attn_mma<<<dim3(LL / 64, HH, BB), 128, ATTN_SMEM>>>();

    // out projection
    fp16_gemm<<<dim3(EE / 128, NTOK / 128), 256, GEMM_SMEM>>>(bout, out, 1);
}

// round 15
// speedup vs baseline: 2.0460x; 1.2552x over previous
#include <cuda_runtime.h>
#include <cuda_fp16.h>
#include <cstdint>
#include <math.h>

// Problem constants
#define BB   2
#define LL   4096
#define EE   512
#define HH   8
#define DD   64
#define WIN  128
#define NTOK (BB*LL)          // 8192
#define QKVN (3*EE)           // 1536

// ---------------------------------------------------------------------------
// Device scratch (half precision dataflow)
// ---------------------------------------------------------------------------
__device__ __half g_Xh[NTOK*EE];                      // x rounded
__device__ __half g_Wq[QKVN*EE];                      // qkv weights (rounded)
__device__ __half g_Wo[EE*EE];                        // out weights (rounded)
__device__ __half g_Qh[BB*HH*LL*DD];                  // Q rounded (scaled)
__device__ __half g_Kh[BB*HH*LL*DD];                  // K rounded [B,H,L,D]
__device__ __half g_Vt[BB*HH*DD*LL];                  // V transposed [B,H,D,L]
__device__ __half g_Oh[BB*LL*EE];                     // attn out (rounded)

// ---------------------------------------------------------------------------
// Helpers
// ---------------------------------------------------------------------------
__device__ __forceinline__ void mma_f16(float* d, const uint32_t* a,
                                        const uint32_t* b) {
    asm volatile(
        "mma.sync.aligned.m16n8k16.row.col.f32.f16.f16.f32 "
        "{%0,%1,%2,%3}, {%4,%5,%6,%7}, {%8,%9}, {%0,%1,%2,%3};"
        : "+f"(d[0]), "+f"(d[1]), "+f"(d[2]), "+f"(d[3])
        : "r"(a[0]), "r"(a[1]), "r"(a[2]), "r"(a[3]),
          "r"(b[0]), "r"(b[1]));
}

#define LDSM4(r0, r1, r2, r3, addr) \
    asm volatile("ldmatrix.sync.aligned.m8n8.x4.shared.b16 {%0,%1,%2,%3}, [%4];" \
                 : "=r"(r0), "=r"(r1), "=r"(r2), "=r"(r3) : "r"(addr))

__device__ __forceinline__ uint32_t pack_h2(__half a, __half b) {
    return (uint32_t)__half_as_ushort(a) | ((uint32_t)__half_as_ushort(b) << 16);
}

__device__ __forceinline__ uint32_t smem_u32(const void* p) {
    uint32_t a;
    asm("{ .reg .u64 t; cvta.to.shared.u64 t, %1; cvt.u32.u64 %0, t; }"
        : "=r"(a) : "l"(p));
    return a;
}
// L2-only (cg): streamed data, don't pollute L1 (LDSM needs its bandwidth)
__device__ __forceinline__ void cp16(uint32_t dst, const void* src) {
    asm volatile("cp.async.cg.shared.global [%0], [%1], 16;"
                 :: "r"(dst), "l"(src));
}
#define CP_COMMIT() asm volatile("cp.async.commit_group;" ::: "memory")

// ---------------------------------------------------------------------------
// Prep: round f32 arrays to half.  which: 0=Wq 1=Wo 2=X
// ---------------------------------------------------------------------------
__global__ __launch_bounds__(256) void prep_round(const float* __restrict__ w,
                                                  int which)
{
    __half* dst = (which == 0) ? g_Wq : (which == 1) ? g_Wo : g_Xh;
    int i = (blockIdx.x * 256 + threadIdx.x) * 4;
    float4 v = *reinterpret_cast<const float4*>(&w[i]);
    uint2 u;
    u.x = pack_h2(__float2half_rn(v.x), __float2half_rn(v.y));
    u.y = pack_h2(__float2half_rn(v.z), __float2half_rn(v.w));
    *reinterpret_cast<uint2*>(&dst[i]) = u;
}

// ---------------------------------------------------------------------------
// fp16 m16n8k16 GEMM: C = Ah[M,K] @ Bh[N,K]^T + bias, K=512.
//   CTA 128x128, BK=64 (8 chunks), 8 warps, warp tile 64x32.
//   3-stage cp.async pipeline, ldmatrix.x4 fragment loads.
//   Pitch 72 halves (144B ≡ 16 mod 128): LDSM row addresses conflict-free.
//   (Round-12 proven configuration; regs ~92, 2 CTAs/SM, no spills.)
// ---------------------------------------------------------------------------
#define HP   72
#define PLH  (128 * HP)                 // halves per plane
#define GEMM_SMEM (6 * PLH * 2)         // 3 stages x (A | B) = 108 KB

__global__ __launch_bounds__(256) void fp16_gemm(
    const float* __restrict__ bias, float* __restrict__ outp, int mode)
{
    extern __shared__ __half smh[];
    const uint32_t sbase = smem_u32(smh);

    const int tid = threadIdx.x;
    const int m0 = blockIdx.y * 128;
    const int n0 = blockIdx.x * 128;

    const __half* Ahg = mode ? g_Oh : g_Xh;
    const __half* Bg  = mode ? g_Wo : g_Wq;

    const int w    = tid >> 5;
    const int lane = tid & 31;
    const int g    = lane >> 2;
    const int c    = lane & 3;
    const int rm   = (w >> 2) * 64;
    const int cn   = (w & 3) * 32;

    // ldmatrix lane-address components
    const int arow = lane & 15;
    const int acol = (lane >> 4) * 8;
    const int bno  = (lane & 7) + ((lane >> 4) << 3);
    const int bko  = ((lane >> 3) & 1) * 8;

    float acc[4][4][4];
    #pragma unroll
    for (int mi = 0; mi < 4; mi++)
        #pragma unroll
        for (int ni = 0; ni < 4; ni++)
            #pragma unroll
            for (int r = 0; r < 4; r++) acc[mi][ni][r] = 0.f;

    const int lrow = tid >> 2;           // 0..63
    const int lcol = (tid & 3) * 16;     // 0,16,32,48 (halves)

    auto issue_chunk = [&](int kc, int p) {
        const __half* a  = Ahg + (size_t)m0 * EE + kc * 64;
        const __half* bb = Bg  + (size_t)n0 * EE + kc * 64;
        const uint32_t sb = sbase + (uint32_t)(p * 2 * PLH * 2);
        #pragma unroll
        for (int i = 0; i < 2; i++) {
            int row = lrow + i * 64;
            uint32_t so = (uint32_t)((row * HP + lcol) * 2);
            cp16(sb + so,                a  + (size_t)row * EE + lcol);
            cp16(sb + so + 16,           a  + (size_t)row * EE + lcol + 8);
            cp16(sb + PLH * 2 + so,      bb + (size_t)row * EE + lcol);
            cp16(sb + PLH * 2 + so + 16, bb + (size_t)row * EE + lcol + 8);
        }
    };

    issue_chunk(0, 0); CP_COMMIT();
    issue_chunk(1, 1); CP_COMMIT();

    for (int kc = 0; kc < 8; kc++) {
        const int p = kc % 3;
        if (kc < 7) asm volatile("cp.async.wait_group 1;" ::: "memory");
        else        asm volatile("cp.async.wait_group 0;" ::: "memory");
        __syncthreads();

        if (kc + 2 < 8) {
            issue_chunk(kc + 2, (kc + 2) % 3);
            CP_COMMIT();
        }

        const uint32_t sA = sbase + (uint32_t)(p * 2 * PLH * 2);
        const uint32_t sB = sA + (uint32_t)(PLH * 2);

        #pragma unroll
        for (int ks = 0; ks < 4; ks++) {
            uint32_t af[4][4], bf[4][2];
            #pragma unroll
            for (int mi = 0; mi < 4; mi++) {
                uint32_t ad = sA + (uint32_t)(((rm + mi * 16 + arow) * HP
                                               + ks * 16 + acol) * 2);
                LDSM4(af[mi][0], af[mi][1], af[mi][2], af[mi][3], ad);
            }
            #pragma unroll
            for (int p2 = 0; p2 < 2; p2++) {
                uint32_t bd = sB + (uint32_t)(((cn + p2 * 16 + bno) * HP
                                               + ks * 16 + bko) * 2);
                LDSM4(bf[2 * p2][0], bf[2 * p2][1],
                      bf[2 * p2 + 1][0], bf[2 * p2 + 1][1], bd);
            }
            #pragma unroll
            for (int mi = 0; mi < 4; mi++)
                #pragma unroll
                for (int ni = 0; ni < 4; ni++)
                    mma_f16(acc[mi][ni], af[mi], bf[ni]);
        }
    }

    float bv[4][2];
    #pragma unroll
    for (int ni = 0; ni < 4; ni++) {
        int gn = n0 + cn + ni * 8 + 2 * c;
        bv[ni][0] = bias[gn];
        bv[ni][1] = bias[gn + 1];
    }

    if (mode == 0) {
        const int gnb = n0 + cn;
        const int sel = gnb >> 9;                  // 0=Q 1=K 2=V
        const int h   = (gnb >> 6) & 7;
        #pragma unroll
        for (int mi = 0; mi < 4; mi++) {
            #pragma unroll
            for (int half = 0; half < 2; half++) {
                int gm  = m0 + rm + mi * 16 + g + half * 8;
                int bat = gm >> 12;
                int l   = gm & (LL - 1);
                #pragma unroll
                for (int ni = 0; ni < 4; ni++) {
                    int gn = n0 + cn + ni * 8 + 2 * c;
                    int d  = gn & 63;
                    float f0 = acc[mi][ni][half * 2 + 0] + bv[ni][0];
                    float f1 = acc[mi][ni][half * 2 + 1] + bv[ni][1];
                    if (sel == 0) {
                        f0 *= 0.125f; f1 *= 0.125f;
                        size_t rb = (((size_t)(bat * HH + h) * LL) + l) * DD + d;
                        *reinterpret_cast<uint32_t*>(&g_Qh[rb]) =
                            pack_h2(__float2half_rn(f0), __float2half_rn(f1));
                    } else if (sel == 1) {
                        size_t rb = (((size_t)(bat * HH + h) * LL) + l) * DD + d;
                        *reinterpret_cast<uint32_t*>(&g_Kh[rb]) =
                            pack_h2(__float2half_rn(f0), __float2half_rn(f1));
                    } else {
                        size_t vb = (((size_t)(bat * HH + h) * DD) + d) * LL + l;
                        g_Vt[vb]      = __float2half_rn(f0);
                        g_Vt[vb + LL] = __float2half_rn(f1);
                    }
                }
            }
        }
    } else {
        #pragma unroll
        for (int mi = 0; mi < 4; mi++) {
            #pragma unroll
            for (int half = 0; half < 2; half++) {
                int gm = m0 + rm + mi * 16 + g + half * 8;
                #pragma unroll
                for (int ni = 0; ni < 4; ni++) {
                    int gn = n0 + cn + ni * 8 + 2 * c;
                    float2 o;
                    o.x = acc[mi][ni][half * 2 + 0] + bv[ni][0];
                    o.y = acc[mi][ni][half * 2 + 1] + bv[ni][1];
                    *reinterpret_cast<float2*>(&outp[(size_t)gm * EE + gn]) = o;
                }
            }
        }
    }
}

// ---------------------------------------------------------------------------
// Banded flash attention, fp16 m16n8k16, single-rounded operands, ldmatrix.
//   Planes (half, pitch 72): Qs | Ks | Vt | Ph. 36 KB -> 4+ CTAs/SM.
//   (Round-12 proven configuration.)
// ---------------------------------------------------------------------------
#define AP 72
#define HPL (64 * AP)
#define ATTN_SMEM (4 * HPL * 2)

__global__ __launch_bounds__(128, 4) void attn_mma()
{
    extern __shared__ __half smq[];
    const uint32_t sQ = smem_u32(smq);
    const uint32_t sK = sQ + 1 * HPL * 2;
    const uint32_t sV = sQ + 2 * HPL * 2;
    const uint32_t sP = sQ + 3 * HPL * 2;
    __half* Qs = smq;
    __half* Ks = smq + 1 * HPL;
    __half* Vt = smq + 2 * HPL;
    __half* Ph = smq + 3 * HPL;

    const int q0 = blockIdx.x * 64;
    const int h  = blockIdx.y;
    const int b  = blockIdx.z;
    const int tid  = threadIdx.x;
    const int w    = tid >> 5;
    const int lane = tid & 31;
    const int g    = lane >> 2;
    const int c    = lane & 3;

    const int arow = lane & 15;
    const int acol = (lane >> 4) * 8;
    const int bno  = (lane & 7) + ((lane >> 4) << 3);
    const int bko  = ((lane >> 3) & 1) * 8;

    const size_t khead = ((size_t)(b * HH + h) * LL) * DD;
    const size_t vhead = ((size_t)(b * HH + h) * DD) * LL;

    // ---- stage Q (pure copy) ----
    #pragma unroll
    for (int i = 0; i < 4; i++) {
        int u = tid + i * 128;
        int row = u >> 3;
        int seg = (u & 7) * 8;
        *reinterpret_cast<uint4*>(&Qs[row * AP + seg]) =
            *reinterpret_cast<const uint4*>(&g_Qh[khead + (size_t)(q0 + row) * DD + seg]);
    }

    float om[2] = {-1e30f, -1e30f};
    float ol[2] = {0.f, 0.f};
    float oacc[8][4];
    #pragma unroll
    for (int nt = 0; nt < 8; nt++)
        #pragma unroll
        for (int r = 0; r < 4; r++) oacc[nt][r] = 0.f;

    __syncthreads();

    const int row_lo = 16 * w + g;
    const int q_lo = q0 + row_lo;
    const int q_hi = q_lo + 8;

    for (int ch = 0; ch < 5; ch++) {
        const int kcc = q0 - 128 + ch * 64;
        if (kcc + 64 <= 0 || kcc >= LL) continue;

        // ---- stage K (natural) and V (pre-transposed) — pure copies ----
        #pragma unroll
        for (int i = 0; i < 4; i++) {
            int u = tid + i * 128;
            int row = u >> 3;
            int seg = (u & 7) * 8;
            int kk = min(max(kcc + row, 0), LL - 1);
            *reinterpret_cast<uint4*>(&Ks[row * AP + seg]) =
                *reinterpret_cast<const uint4*>(&g_Kh[khead + (size_t)kk * DD + seg]);
            int kb = min(max(kcc + seg, 0), LL - 8);
            *reinterpret_cast<uint4*>(&Vt[row * AP + seg]) =
                *reinterpret_cast<const uint4*>(&g_Vt[vhead + (size_t)row * LL + kb]);
        }
        __syncthreads();

        // ---- scores: Q @ K^T (ldmatrix + single MMA per tile) ----
        float sacc[8][4];
        #pragma unroll
        for (int nt = 0; nt < 8; nt++)
            #pragma unroll
            for (int r = 0; r < 4; r++) sacc[nt][r] = 0.f;

        #pragma unroll
        for (int ks = 0; ks < 4; ks++) {
            uint32_t af[4], kb2[8][2];
            uint32_t ad = sQ + (uint32_t)(((16 * w + arow) * AP + ks * 16 + acol) * 2);
            LDSM4(af[0], af[1], af[2], af[3], ad);
            #pragma unroll
            for (int p2 = 0; p2 < 4; p2++) {
                uint32_t bd = sK + (uint32_t)(((p2 * 16 + bno) * AP + ks * 16 + bko) * 2);
                LDSM4(kb2[2 * p2][0], kb2[2 * p2][1],
                      kb2[2 * p2 + 1][0], kb2[2 * p2 + 1][1], bd);
            }
            #pragma unroll
            for (int nt = 0; nt < 8; nt++)
                mma_f16(sacc[nt], af, kb2[nt]);
        }

        // ---- mask ----
        #pragma unroll
        for (int nt = 0; nt < 8; nt++) {
            #pragma unroll
            for (int r = 0; r < 4; r++) {
                int key = kcc + nt * 8 + 2 * c + (r & 1);
                int q   = (r >> 1) ? q_hi : q_lo;
                int dlt = q - key;
                bool ok = (key >= 0) && (key < LL) && (dlt != 0) &&
                          (dlt <= WIN) && (dlt >= -WIN);
                if (!ok) sacc[nt][r] = -1e30f;
            }
        }

        // ---- online softmax; write P (single fp16) ----
        float mx0 = -1e30f, mx1 = -1e30f;
        #pragma unroll
        for (int nt = 0; nt < 8; nt++) {
            mx0 = fmaxf(mx0, fmaxf(sacc[nt][0], sacc[nt][1]));
            mx1 = fmaxf(mx1, fmaxf(sacc[nt][2], sacc[nt][3]));
        }
        mx0 = fmaxf(mx0, __shfl_xor_sync(0xffffffffu, mx0, 1));
        mx0 = fmaxf(mx0, __shfl_xor_sync(0xffffffffu, mx0, 2));
        mx1 = fmaxf(mx1, __shfl_xor_sync(0xffffffffu, mx1, 1));
        mx1 = fmaxf(mx1, __shfl_xor_sync(0xffffffffu, mx1, 2));

        float m0n = fmaxf(om[0], mx0);
        float m1n = fmaxf(om[1], mx1);
        float alpha0 = __expf(om[0] - m0n);
        float alpha1 = __expf(om[1] - m1n);

        float sum0 = 0.f, sum1 = 0.f;
        #pragma unroll
        for (int nt = 0; nt < 8; nt++) {
            float p0 = __expf(sacc[nt][0] - m0n);
            float p1 = __expf(sacc[nt][1] - m0n);
            float p2 = __expf(sacc[nt][2] - m1n);
            float p3 = __expf(sacc[nt][3] - m1n);
            sum0 += p0 + p1;
            sum1 += p2 + p3;
            const int pi_lo = row_lo * AP + nt * 8 + 2 * c;
            const int pi_hi = pi_lo + 8 * AP;
            *reinterpret_cast<uint32_t*>(&Ph[pi_lo]) =
                pack_h2(__float2half_rn(p0), __float2half_rn(p1));
            *reinterpret_cast<uint32_t*>(&Ph[pi_hi]) =
                pack_h2(__float2half_rn(p2), __float2half_rn(p3));
        }
        sum0 += __shfl_xor_sync(0xffffffffu, sum0, 1);
        sum0 += __shfl_xor_sync(0xffffffffu, sum0, 2);
        sum1 += __shfl_xor_sync(0xffffffffu, sum1, 1);
        sum1 += __shfl_xor_sync(0xffffffffu, sum1, 2);

        ol[0] = ol[0] * alpha0 + sum0;
        ol[1] = ol[1] * alpha1 + sum1;
        om[0] = m0n;
        om[1] = m1n;

        #pragma unroll
        for (int nt = 0; nt < 8; nt++) {
            oacc[nt][0] *= alpha0;
            oacc[nt][1] *= alpha0;
            oacc[nt][2] *= alpha1;
            oacc[nt][3] *= alpha1;
        }
        __syncwarp();   // P rows are warp-private

        // ---- O += P @ V (ldmatrix + single MMA per tile) ----
        #pragma unroll
        for (int ks = 0; ks < 4; ks++) {
            uint32_t af[4], vb2[8][2];
            uint32_t ad = sP + (uint32_t)(((16 * w + arow) * AP + ks * 16 + acol) * 2);
            LDSM4(af[0], af[1], af[2], af[3], ad);
            #pragma unroll
            for (int p2 = 0; p2 < 4; p2++) {
                uint32_t bd = sV + (uint32_t)(((p2 * 16 + bno) * AP + ks * 16 + bko) * 2);
                LDSM4(vb2[2 * p2][0], vb2[2 * p2][1],
                      vb2[2 * p2 + 1][0], vb2[2 * p2 + 1][1], bd);
            }
            #pragma unroll
            for (int nt = 0; nt < 8; nt++)
                mma_f16(oacc[nt], af, vb2[nt]);
        }
        __syncthreads();   // protect Ks/Vt before next chunk staging
    }

    // ---- epilogue: normalize, round, write Oh [B,L,E] ----
    const float inv0 = 1.f / ol[0];
    const float inv1 = 1.f / ol[1];
    const size_t base_lo = ((size_t)(b * LL + q_lo)) * EE + h * DD;
    const size_t base_hi = ((size_t)(b * LL + q_hi)) * EE + h * DD;
    #pragma unroll
    for (int nt = 0; nt < 8; nt++) {
        int d = nt * 8 + 2 * c;
        *reinterpret_cast<uint32_t*>(&g_Oh[base_lo + d]) =
            pack_h2(__float2half_rn(oacc[nt][0] * inv0),
                    __float2half_rn(oacc[nt][1] * inv0));
        *reinterpret_cast<uint32_t*>(&g_Oh[base_hi + d]) =
            pack_h2(__float2half_rn(oacc[nt][2] * inv1),
                    __float2half_rn(oacc[nt][3] * inv1));
    }
}

// ---------------------------------------------------------------------------
// Entry point
// ---------------------------------------------------------------------------
extern "C" void kernel_launch(void* const* d_in, const int* in_sizes, int n_in,
                              void* d_out, int out_size)
{
    const float* x    = (const float*)d_in[0];   // [B,L,E]
    const float* wqkv = (const float*)d_in[1];   // [3E,E]
    const float* bqkv = (const float*)d_in[2];   // [3E]
    const float* wout = (const float*)d_in[3];   // [E,E]
    const float* bout = (const float*)d_in[4];   // [E]
    float* out = (float*)d_out;                  // [B,L,E]

    (void)in_sizes; (void)n_in; (void)out_size;

    cudaFuncSetAttribute(fp16_gemm, cudaFuncAttributeMaxDynamicSharedMemorySize,
                         GEMM_SMEM);
    cudaFuncSetAttribute(attn_mma, cudaFuncAttributeMaxDynamicSharedMemorySize,
                         ATTN_SMEM);

    // prep: round weights + x to half
    prep_round<<<QKVN * EE / 1024, 256>>>(wqkv, 0);
    prep_round<<<EE * EE / 1024, 256>>>(wout, 1);
    prep_round<<<NTOK * EE / 1024, 256>>>(x, 2);

    // QKV projection
    fp16_gemm<<<dim3(QKVN / 128, NTOK / 128), 256, GEMM_SMEM>>>(bqkv, nullptr, 0);

    // banded attention
    attn_mma<<<dim3(LL / 64, HH, BB), 128, ATTN_SMEM>>>();

    // out projection
    fp16_gemm<<<dim3(EE / 128, NTOK / 128), 256, GEMM_SMEM>>>(bout, out, 1);
}

// round 16
// speedup vs baseline: 2.2259x; 1.0879x over previous
#include <cuda_runtime.h>
#include <cuda_fp16.h>
#include <cstdint>
#include <math.h>

// Problem constants
#define BB   2
#define LL   4096
#define EE   512
#define HH   8
#define DD   64
#define WIN  128
#define NTOK (BB*LL)          // 8192
#define QKVN (3*EE)           // 1536

// ---------------------------------------------------------------------------
// Device scratch (half precision dataflow)
// ---------------------------------------------------------------------------
__device__ __half g_Xh[NTOK*EE];                      // x rounded
__device__ __half g_Wq[QKVN*EE];                      // qkv weights (rounded)
__device__ __half g_Wo[EE*EE];                        // out weights (rounded)
__device__ __half g_Qh[BB*HH*LL*DD];                  // Q rounded (scale*log2e)
__device__ __half g_Kh[BB*HH*LL*DD];                  // K rounded [B,H,L,D]
__device__ __half g_Vt[BB*HH*DD*LL];                  // V transposed [B,H,D,L]
__device__ __half g_Oh[BB*LL*EE];                     // attn out (rounded)

// ---------------------------------------------------------------------------
// Helpers
// ---------------------------------------------------------------------------
__device__ __forceinline__ void mma_f16(float* d, const uint32_t* a,
                                        const uint32_t* b) {
    asm volatile(
        "mma.sync.aligned.m16n8k16.row.col.f32.f16.f16.f32 "
        "{%0,%1,%2,%3}, {%4,%5,%6,%7}, {%8,%9}, {%0,%1,%2,%3};"
        : "+f"(d[0]), "+f"(d[1]), "+f"(d[2]), "+f"(d[3])
        : "r"(a[0]), "r"(a[1]), "r"(a[2]), "r"(a[3]),
          "r"(b[0]), "r"(b[1]));
}

#define LDSM4(r0, r1, r2, r3, addr) \
    asm volatile("ldmatrix.sync.aligned.m8n8.x4.shared.b16 {%0,%1,%2,%3}, [%4];" \
                 : "=r"(r0), "=r"(r1), "=r"(r2), "=r"(r3) : "r"(addr))

__device__ __forceinline__ uint32_t pack_h2(__half a, __half b) {
    return (uint32_t)__half_as_ushort(a) | ((uint32_t)__half_as_ushort(b) << 16);
}

__device__ __forceinline__ uint32_t smem_u32(const void* p) {
    uint32_t a;
    asm("{ .reg .u64 t; cvta.to.shared.u64 t, %1; cvt.u32.u64 %0, t; }"
        : "=r"(a) : "l"(p));
    return a;
}
// L2-only (cg): streamed data, don't pollute L1 (LDSM needs its bandwidth)
__device__ __forceinline__ void cp16(uint32_t dst, const void* src) {
    asm volatile("cp.async.cg.shared.global [%0], [%1], 16;"
                 :: "r"(dst), "l"(src));
}
#define CP_COMMIT() asm volatile("cp.async.commit_group;" ::: "memory")

// ---------------------------------------------------------------------------
// Fused prep: round Wq | Wo | X to half in ONE launch (region by linear idx).
// ---------------------------------------------------------------------------
#define WQ_U (QKVN * EE / 4)          // 196608 float4 units
#define WO_U (EE * EE / 4)            // 65536
#define X_U  (NTOK * EE / 4)          // 1048576
#define PREP_BLOCKS ((WQ_U + WO_U + X_U) / 256)

__global__ __launch_bounds__(256) void prep_all(
    const float* __restrict__ wq, const float* __restrict__ wo,
    const float* __restrict__ x)
{
    int u = blockIdx.x * 256 + threadIdx.x;
    const float* src;
    __half* dst;
    int off;
    if (u < WQ_U)              { src = wq; dst = g_Wq; off = u; }
    else if (u < WQ_U + WO_U)  { src = wo; dst = g_Wo; off = u - WQ_U; }
    else                       { src = x;  dst = g_Xh; off = u - WQ_U - WO_U; }
    int i = off * 4;
    float4 v = *reinterpret_cast<const float4*>(&src[i]);
    uint2 o;
    o.x = pack_h2(__float2half_rn(v.x), __float2half_rn(v.y));
    o.y = pack_h2(__float2half_rn(v.z), __float2half_rn(v.w));
    *reinterpret_cast<uint2*>(&dst[i]) = o;
}

// ---------------------------------------------------------------------------
// fp16 m16n8k16 GEMM: C = Ah[M,K] @ Bh[N,K]^T + bias, K=512.
//   CTA 128x128, BK=64 (8 chunks), 8 warps, warp tile 64x32.
//   3-stage cp.async pipeline, ldmatrix.x4.  (Round-15 proven: 58 us qkv.)
// ---------------------------------------------------------------------------
#define HP   72
#define PLH  (128 * HP)
#define GEMM_SMEM (6 * PLH * 2)         // 108 KB

__global__ __launch_bounds__(256) void fp16_gemm(
    const float* __restrict__ bias, float* __restrict__ outp, int mode)
{
    extern __shared__ __half smh[];
    const uint32_t sbase = smem_u32(smh);

    const int tid = threadIdx.x;
    const int m0 = blockIdx.y * 128;
    const int n0 = blockIdx.x * 128;

    const __half* Ahg = mode ? g_Oh : g_Xh;
    const __half* Bg  = mode ? g_Wo : g_Wq;

    const int w    = tid >> 5;
    const int lane = tid & 31;
    const int g    = lane >> 2;
    const int c    = lane & 3;
    const int rm   = (w >> 2) * 64;
    const int cn   = (w & 3) * 32;

    const int arow = lane & 15;
    const int acol = (lane >> 4) * 8;
    const int bno  = (lane & 7) + ((lane >> 4) << 3);
    const int bko  = ((lane >> 3) & 1) * 8;

    float acc[4][4][4];
    #pragma unroll
    for (int mi = 0; mi < 4; mi++)
        #pragma unroll
        for (int ni = 0; ni < 4; ni++)
            #pragma unroll
            for (int r = 0; r < 4; r++) acc[mi][ni][r] = 0.f;

    const int lrow = tid >> 2;
    const int lcol = (tid & 3) * 16;

    auto issue_chunk = [&](int kc, int p) {
        const __half* a  = Ahg + (size_t)m0 * EE + kc * 64;
        const __half* bb = Bg  + (size_t)n0 * EE + kc * 64;
        const uint32_t sb = sbase + (uint32_t)(p * 2 * PLH * 2);
        #pragma unroll
        for (int i = 0; i < 2; i++) {
            int row = lrow + i * 64;
            uint32_t so = (uint32_t)((row * HP + lcol) * 2);
            cp16(sb + so,                a  + (size_t)row * EE + lcol);
            cp16(sb + so + 16,           a  + (size_t)row * EE + lcol + 8);
            cp16(sb + PLH * 2 + so,      bb + (size_t)row * EE + lcol);
            cp16(sb + PLH * 2 + so + 16, bb + (size_t)row * EE + lcol + 8);
        }
    };

    issue_chunk(0, 0); CP_COMMIT();
    issue_chunk(1, 1); CP_COMMIT();

    for (int kc = 0; kc < 8; kc++) {
        const int p = kc % 3;
        if (kc < 7) asm volatile("cp.async.wait_group 1;" ::: "memory");
        else        asm volatile("cp.async.wait_group 0;" ::: "memory");
        __syncthreads();

        if (kc + 2 < 8) {
            issue_chunk(kc + 2, (kc + 2) % 3);
            CP_COMMIT();
        }

        const uint32_t sA = sbase + (uint32_t)(p * 2 * PLH * 2);
        const uint32_t sB = sA + (uint32_t)(PLH * 2);

        #pragma unroll
        for (int ks = 0; ks < 4; ks++) {
            uint32_t af[4][4], bf[4][2];
            #pragma unroll
            for (int mi = 0; mi < 4; mi++) {
                uint32_t ad = sA + (uint32_t)(((rm + mi * 16 + arow) * HP
                                               + ks * 16 + acol) * 2);
                LDSM4(af[mi][0], af[mi][1], af[mi][2], af[mi][3], ad);
            }
            #pragma unroll
            for (int p2 = 0; p2 < 2; p2++) {
                uint32_t bd = sB + (uint32_t)(((cn + p2 * 16 + bno) * HP
                                               + ks * 16 + bko) * 2);
                LDSM4(bf[2 * p2][0], bf[2 * p2][1],
                      bf[2 * p2 + 1][0], bf[2 * p2 + 1][1], bd);
            }
            #pragma unroll
            for (int mi = 0; mi < 4; mi++)
                #pragma unroll
                for (int ni = 0; ni < 4; ni++)
                    mma_f16(acc[mi][ni], af[mi], bf[ni]);
        }
    }

    float bv[4][2];
    #pragma unroll
    for (int ni = 0; ni < 4; ni++) {
        int gn = n0 + cn + ni * 8 + 2 * c;
        bv[ni][0] = bias[gn];
        bv[ni][1] = bias[gn + 1];
    }

    if (mode == 0) {
        const int gnb = n0 + cn;
        const int sel = gnb >> 9;                  // 0=Q 1=K 2=V
        const int h   = (gnb >> 6) & 7;
        // Q scale folds 1/sqrt(D) AND log2(e) so softmax can use exp2.
        const float QSCALE = 0.125f * 1.4426950408889634f;
        #pragma unroll
        for (int mi = 0; mi < 4; mi++) {
            #pragma unroll
            for (int half = 0; half < 2; half++) {
                int gm  = m0 + rm + mi * 16 + g + half * 8;
                int bat = gm >> 12;
                int l   = gm & (LL - 1);
                #pragma unroll
                for (int ni = 0; ni < 4; ni++) {
                    int gn = n0 + cn + ni * 8 + 2 * c;
                    int d  = gn & 63;
                    float f0 = acc[mi][ni][half * 2 + 0] + bv[ni][0];
                    float f1 = acc[mi][ni][half * 2 + 1] + bv[ni][1];
                    if (sel == 0) {
                        f0 *= QSCALE; f1 *= QSCALE;
                        size_t rb = (((size_t)(bat * HH + h) * LL) + l) * DD + d;
                        *reinterpret_cast<uint32_t*>(&g_Qh[rb]) =
                            pack_h2(__float2half_rn(f0), __float2half_rn(f1));
                    } else if (sel == 1) {
                        size_t rb = (((size_t)(bat * HH + h) * LL) + l) * DD + d;
                        *reinterpret_cast<uint32_t*>(&g_Kh[rb]) =
                            pack_h2(__float2half_rn(f0), __float2half_rn(f1));
                    } else {
                        size_t vb = (((size_t)(bat * HH + h) * DD) + d) * LL + l;
                        g_Vt[vb]      = __float2half_rn(f0);
                        g_Vt[vb + LL] = __float2half_rn(f1);
                    }
                }
            }
        }
    } else {
        #pragma unroll
        for (int mi = 0; mi < 4; mi++) {
            #pragma unroll
            for (int half = 0; half < 2; half++) {
                int gm = m0 + rm + mi * 16 + g + half * 8;
                #pragma unroll
                for (int ni = 0; ni < 4; ni++) {
                    int gn = n0 + cn + ni * 8 + 2 * c;
                    float2 o;
                    o.x = acc[mi][ni][half * 2 + 0] + bv[ni][0];
                    o.y = acc[mi][ni][half * 2 + 1] + bv[ni][1];
                    *reinterpret_cast<float2*>(&outp[(size_t)gm * EE + gn]) = o;
                }
            }
        }
    }
}

// ---------------------------------------------------------------------------
// Banded flash attention, fp16 m16n8k16, ldmatrix, cp.async double-buffered
// K/V staging (valid chunk range precomputed -> clean pipeline, no clamps).
//   Planes (half, pitch 72): Qs | Ph | Ks0 | Vt0 | Ks1 | Vt1. 54 KB -> 4 CTA/SM.
//   Scores carry log2e (folded into Q) -> exp2f softmax (same softmax).
// ---------------------------------------------------------------------------
#define AP 72
#define HPL (64 * AP)
#define ATTN_SMEM (6 * HPL * 2)

__global__ __launch_bounds__(128, 4) void attn_mma()
{
    extern __shared__ __half smq[];
    const uint32_t sQ  = smem_u32(smq);
    const uint32_t sP  = sQ + 1 * HPL * 2;
    const uint32_t sKV = sQ + 2 * HPL * 2;   // two (K,V) buffers of 2 planes
    __half* Qs = smq;

    const int q0 = blockIdx.x * 64;
    const int h  = blockIdx.y;
    const int b  = blockIdx.z;
    const int tid  = threadIdx.x;
    const int w    = tid >> 5;
    const int lane = tid & 31;
    const int g    = lane >> 2;
    const int c    = lane & 3;

    const int arow = lane & 15;
    const int acol = (lane >> 4) * 8;
    const int bno  = (lane & 7) + ((lane >> 4) << 3);
    const int bko  = ((lane >> 3) & 1) * 8;

    const size_t khead = ((size_t)(b * HH + h) * LL) * DD;
    const size_t vhead = ((size_t)(b * HH + h) * DD) * LL;

    // ---- stage Q (pure copy) ----
    #pragma unroll
    for (int i = 0; i < 4; i++) {
        int u = tid + i * 128;
        int row = u >> 3;
        int seg = (u & 7) * 8;
        *reinterpret_cast<uint4*>(&Qs[row * AP + seg]) =
            *reinterpret_cast<const uint4*>(&g_Qh[khead + (size_t)(q0 + row) * DD + seg]);
    }

    // valid chunk range: kcc = q0-128+ch*64 in [0, LL-64]
    const int ch_lo = max(0, (191 - q0) / 64);
    const int ch_hi = min(5, (LL + 128 - q0) / 64);

    // staging via cp.async (no clamps needed inside valid range)
    auto stage_kv = [&](int ch, int p) {
        const int kcc = q0 - 128 + ch * 64;
        const uint32_t sb = sKV + (uint32_t)(p * 2 * HPL * 2);
        #pragma unroll
        for (int i = 0; i < 4; i++) {
            int u = tid + i * 128;
            int row = u >> 3;
            int seg = (u & 7) * 8;
            uint32_t so = (uint32_t)((row * AP + seg) * 2);
            cp16(sb + so, &g_Kh[khead + (size_t)(kcc + row) * DD + seg]);
            cp16(sb + HPL * 2 + so,
                 &g_Vt[vhead + (size_t)row * LL + kcc + seg]);
        }
    };

    float om[2] = {-1e30f, -1e30f};
    float ol[2] = {0.f, 0.f};
    float oacc[8][4];
    #pragma unroll
    for (int nt = 0; nt < 8; nt++)
        #pragma unroll
        for (int r = 0; r < 4; r++) oacc[nt][r] = 0.f;

    stage_kv(ch_lo, 0); CP_COMMIT();
    __syncthreads();     // Q visible to all warps

    const int row_lo = 16 * w + g;
    const int q_lo = q0 + row_lo;
    const int q_hi = q_lo + 8;

    for (int ch = ch_lo; ch < ch_hi; ch++) {
        const int p = (ch - ch_lo) & 1;
        const int kcc = q0 - 128 + ch * 64;
        const uint32_t sK = sKV + (uint32_t)(p * 2 * HPL * 2);
        const uint32_t sV = sK + (uint32_t)(HPL * 2);

        asm volatile("cp.async.wait_group 0;" ::: "memory");
        __syncthreads();                  // data ready AND prior reads done

        if (ch + 1 < ch_hi) {
            stage_kv(ch + 1, p ^ 1);
            CP_COMMIT();
        }

        // ---- scores: Q @ K^T ----
        float sacc[8][4];
        #pragma unroll
        for (int nt = 0; nt < 8; nt++)
            #pragma unroll
            for (int r = 0; r < 4; r++) sacc[nt][r] = 0.f;

        #pragma unroll
        for (int ks = 0; ks < 4; ks++) {
            uint32_t af[4], kb2[8][2];
            uint32_t ad = sQ + (uint32_t)(((16 * w + arow) * AP + ks * 16 + acol) * 2);
            LDSM4(af[0], af[1], af[2], af[3], ad);
            #pragma unroll
            for (int p2 = 0; p2 < 4; p2++) {
                uint32_t bd = sK + (uint32_t)(((p2 * 16 + bno) * AP + ks * 16 + bko) * 2);
                LDSM4(kb2[2 * p2][0], kb2[2 * p2][1],
                      kb2[2 * p2 + 1][0], kb2[2 * p2 + 1][1], bd);
            }
            #pragma unroll
            for (int nt = 0; nt < 8; nt++)
                mma_f16(sacc[nt], af, kb2[nt]);
        }

        // ---- mask ----
        #pragma unroll
        for (int nt = 0; nt < 8; nt++) {
            #pragma unroll
            for (int r = 0; r < 4; r++) {
                int key = kcc + nt * 8 + 2 * c + (r & 1);
                int q   = (r >> 1) ? q_hi : q_lo;
                int dlt = q - key;
                bool ok = (dlt != 0) && (dlt <= WIN) && (dlt >= -WIN);
                if (!ok) sacc[nt][r] = -1e30f;
            }
        }

        // ---- online softmax (base-2; log2e folded into Q) ----
        float mx0 = -1e30f, mx1 = -1e30f;
        #pragma unroll
        for (int nt = 0; nt < 8; nt++) {
            mx0 = fmaxf(mx0, fmaxf(sacc[nt][0], sacc[nt][1]));
            mx1 = fmaxf(mx1, fmaxf(sacc[nt][2], sacc[nt][3]));
        }
        mx0 = fmaxf(mx0, __shfl_xor_sync(0xffffffffu, mx0, 1));
        mx0 = fmaxf(mx0, __shfl_xor_sync(0xffffffffu, mx0, 2));
        mx1 = fmaxf(mx1, __shfl_xor_sync(0xffffffffu, mx1, 1));
        mx1 = fmaxf(mx1, __shfl_xor_sync(0xffffffffu, mx1, 2));

        float m0n = fmaxf(om[0], mx0);
        float m1n = fmaxf(om[1], mx1);
        float alpha0 = exp2f(om[0] - m0n);
        float alpha1 = exp2f(om[1] - m1n);

        float sum0 = 0.f, sum1 = 0.f;
        __half* Ph = smq + 1 * HPL;
        #pragma unroll
        for (int nt = 0; nt < 8; nt++) {
            float p0 = exp2f(sacc[nt][0] - m0n);
            float p1 = exp2f(sacc[nt][1] - m0n);
            float p2 = exp2f(sacc[nt][2] - m1n);
            float p3 = exp2f(sacc[nt][3] - m1n);
            sum0 += p0 + p1;
            sum1 += p2 + p3;
            const int pi_lo = row_lo * AP + nt * 8 + 2 * c;
            const int pi_hi = pi_lo + 8 * AP;
            *reinterpret_cast<uint32_t*>(&Ph[pi_lo]) =
                pack_h2(__float2half_rn(p0), __float2half_rn(p1));
            *reinterpret_cast<uint32_t*>(&Ph[pi_hi]) =
                pack_h2(__float2half_rn(p2), __float2half_rn(p3));
        }
        sum0 += __shfl_xor_sync(0xffffffffu, sum0, 1);
        sum0 += __shfl_xor_sync(0xffffffffu, sum0, 2);
        sum1 += __shfl_xor_sync(0xffffffffu, sum1, 1);
        sum1 += __shfl_xor_sync(0xffffffffu, sum1, 2);

        ol[0] = ol[0] * alpha0 + sum0;
        ol[1] = ol[1] * alpha1 + sum1;
        om[0] = m0n;
        om[1] = m1n;

        #pragma unroll
        for (int nt = 0; nt < 8; nt++) {
            oacc[nt][0] *= alpha0;
            oacc[nt][1] *= alpha0;
            oacc[nt][2] *= alpha1;
            oacc[nt][3] *= alpha1;
        }
        __syncwarp();   // P rows are warp-private

        // ---- O += P @ V ----
        #pragma unroll
        for (int ks = 0; ks < 4; ks++) {
            uint32_t af[4], vb2[8][2];
            uint32_t ad = sP + (uint32_t)(((16 * w + arow) * AP + ks * 16 + acol) * 2);
            LDSM4(af[0], af[1], af[2], af[3], ad);
            #pragma unroll
            for (int p2 = 0; p2 < 4; p2++) {
                uint32_t bd = sV + (uint32_t)(((p2 * 16 + bno) * AP + ks * 16 + bko) * 2);
                LDSM4(vb2[2 * p2][0], vb2[2 * p2][1],
                      vb2[2 * p2 + 1][0], vb2[2 * p2 + 1][1], bd);
            }
            #pragma unroll
            for (int nt = 0; nt < 8; nt++)
                mma_f16(oacc[nt], af, vb2[nt]);
        }
        // no trailing sync: next iteration's sync (after wait) protects buffers
    }

    // ---- epilogue: normalize, round, write Oh [B,L,E] ----
    const float inv0 = 1.f / ol[0];
    const float inv1 = 1.f / ol[1];
    const size_t base_lo = ((size_t)(b * LL + q_lo)) * EE + h * DD;
    const size_t base_hi = ((size_t)(b * LL + q_hi)) * EE + h * DD;
    #pragma unroll
    for (int nt = 0; nt < 8; nt++) {
        int d = nt * 8 + 2 * c;
        *reinterpret_cast<uint32_t*>(&g_Oh[base_lo + d]) =
            pack_h2(__float2half_rn(oacc[nt][0] * inv0),
                    __float2half_rn(oacc[nt][1] * inv0));
        *reinterpret_cast<uint32_t*>(&g_Oh[base_hi + d]) =
            pack_h2(__float2half_rn(oacc[nt][2] * inv1),
                    __float2half_rn(oacc[nt][3] * inv1));
    }
}

// ---------------------------------------------------------------------------
// Entry point
// ---------------------------------------------------------------------------
extern "C" void kernel_launch(void* const* d_in, const int* in_sizes, int n_in,
                              void* d_out, int out_size)
{
    const float* x    = (const float*)d_in[0];   // [B,L,E]
    const float* wqkv = (const float*)d_in[1];   // [3E,E]
    const float* bqkv = (const float*)d_in[2];   // [3E]
    const float* wout = (const float*)d_in[3];   // [E,E]
    const float* bout = (const float*)d_in[4];   // [E]
    float* out = (float*)d_out;                  // [B,L,E]

    (void)in_sizes; (void)n_in; (void)out_size;

    cudaFuncSetAttribute(fp16_gemm, cudaFuncAttributeMaxDynamicSharedMemorySize,
                         GEMM_SMEM);
    cudaFuncSetAttribute(attn_mma, cudaFuncAttributeMaxDynamicSharedMemorySize,
                         ATTN_SMEM);

    // fused prep: all three conversions in one launch
    prep_all<<<PREP_BLOCKS, 256>>>(wqkv, wout, x);

    // QKV projection
    fp16_gemm<<<dim3(QKVN / 128, NTOK / 128), 256, GEMM_SMEM>>>(bqkv, nullptr, 0);

    // banded attention
    attn_mma<<<dim3(LL / 64, HH, BB), 128, ATTN_SMEM>>>();

    // out projection
    fp16_gemm<<<dim3(EE / 128, NTOK / 128), 256, GEMM_SMEM>>>(bout, out, 1);
}